// round 4
// baseline (speedup 1.0000x reference)
#include <cuda_runtime.h>
#include <cuda_bf16.h>

// Dequant: groups of 17 int32 (16 "byte" ints -> 32 nibbles, 1 scale int).
// out[g*32 + i] = (nibble_i - 8) / 12 * exp2(clamp(scale-127, -126, 127))
//
// Block owns 256 groups (17408 B input, 16B-aligned per block). Input is
// staged through shared memory with fully-coalesced streaming LDG.128,
// then each thread assembles 8 output float4s from smem and stores with
// warp-coalesced STG.128.

#define THREADS 256
#define GROUPS_PER_BLOCK 256
#define INTS_PER_BLOCK  (GROUPS_PER_BLOCK * 17)          // 4352
#define INT4_PER_BLOCK  (INTS_PER_BLOCK / 4)             // 1088
#define QUADS_PER_BLOCK (GROUPS_PER_BLOCK * 8)           // 2048

__global__ void __launch_bounds__(THREADS) dequant_mxfp4_kernel(
    const int* __restrict__ packed,
    float4* __restrict__ out,
    int num_quads)
{
    __shared__ int sm[INTS_PER_BLOCK];

    // --- Stage input: 1088 int4 loads, consecutive threads -> consecutive 16B ---
    const int4* src = (const int4*)(packed + (size_t)blockIdx.x * INTS_PER_BLOCK);
    int4* sm4 = (int4*)sm;
    #pragma unroll
    for (int i = 0; i < 5; i++) {
        int idx = threadIdx.x + i * THREADS;
        if (idx < INT4_PER_BLOCK) {
            sm4[idx] = __ldcs(src + idx);
        }
    }
    __syncthreads();

    // --- Dequant: 8 quads per thread, block-strided for coalesced stores ---
    int q0 = blockIdx.x * QUADS_PER_BLOCK + threadIdx.x;

    #pragma unroll
    for (int j = 0; j < 8; j++) {
        int q  = q0 + j * THREADS;
        if (q >= num_quads) break;
        int lq  = threadIdx.x + j * THREADS;   // local quad 0..2047
        int lg  = lq >> 3;                     // local group
        int sub = lq & 7;
        int base = lg * 17;

        int v0 = sm[base + sub * 2];
        int v1 = sm[base + sub * 2 + 1];
        int s  = sm[base + 16];

        // exp2(clip(s-127,-126,127)) == float with exponent field clamp(s,1,254)
        int e = min(max(s, 1), 254);
        float scale = __int_as_float(e << 23) * (1.0f / 12.0f);

        float4 r;
        r.x = (float)((v0 & 15)        - 8) * scale;
        r.y = (float)(((v0 >> 4) & 15) - 8) * scale;
        r.z = (float)((v1 & 15)        - 8) * scale;
        r.w = (float)(((v1 >> 4) & 15) - 8) * scale;

        __stcs(out + q, r);
    }
}

extern "C" void kernel_launch(void* const* d_in, const int* in_sizes, int n_in,
                              void* d_out, int out_size)
{
    const int* packed = (const int*)d_in[0];
    float4* out = (float4*)d_out;

    int num_quads = out_size / 4;  // 33,554,432
    int blocks = (num_quads + QUADS_PER_BLOCK - 1) / QUADS_PER_BLOCK;  // 16384

    dequant_mxfp4_kernel<<<blocks, THREADS>>>(packed, out, num_quads);
}